// round 1
// baseline (speedup 1.0000x reference)
#include <cuda_runtime.h>
#include <cuda_bf16.h>

#define T_DIM 512
#define B_DIM 128
#define E_DIM 256

// Scratch: coefficient matrix C[t][b][i] (134 MB) + band start index per (t,b).
// __device__ globals (module-load allocated) — no runtime allocation.
__device__ float g_C[T_DIM][B_DIM][T_DIM];
__device__ int   g_lo[T_DIM * B_DIM];

// ---------------------------------------------------------------------------
// Kernel A: per-batch sequential stack scan. One block per batch (b), 512
// threads, thread i owns stack slot i's strength S in a register.
// Per step: two exclusive suffix sums (warp shfl scans + cross-warp totals),
// pop/push update, coefficient computation, band-start via ballot.
// ---------------------------------------------------------------------------
__global__ __launch_bounds__(512, 1) void stack_scan_kernel(
    const float* __restrict__ u, const float* __restrict__ d) {
  const int b    = blockIdx.x;
  const int i    = threadIdx.x;          // stack position
  const int warp = i >> 5;
  const int lane = i & 31;

  __shared__ float tot1[16];
  __shared__ float tot2[16];
  __shared__ int   wlo[16];
  __shared__ float su[T_DIM];
  __shared__ float sd[T_DIM];

  // Preload this batch's pop/push signals (strided gather, done once).
  su[i] = u[i * B_DIM + b];
  sd[i] = d[i * B_DIM + b];
  float S = 0.f;
  __syncthreads();

  for (int t = 0; t < T_DIM; ++t) {
    // ---- scan 1: inclusive suffix sum of old S (within warp) ----
    float val = S;
    #pragma unroll
    for (int off = 1; off < 32; off <<= 1) {
      float o = __shfl_down_sync(0xffffffffu, val, off);
      if (lane + off < 32) val += o;
    }
    if (lane == 0) tot1[warp] = val;
    __syncthreads();                                   // bar 1
    float above = 0.f;
    #pragma unroll
    for (int w = 0; w < 16; ++w)
      if (w > warp) above += tot1[w];

    // R = exclusive suffix sum over old S; pop phase
    float R    = val + above - S;
    float wpop = fmaxf(su[t] - R, 0.f);
    S = fmaxf(S - wpop, 0.f);
    // push phase
    if (i == t) S = sd[t];

    // ---- scan 2: inclusive suffix sum of new S ----
    val = S;
    #pragma unroll
    for (int off = 1; off < 32; off <<= 1) {
      float o = __shfl_down_sync(0xffffffffu, val, off);
      if (lane + off < 32) val += o;
    }
    if (lane == 0) tot2[warp] = val;
    __syncthreads();                                   // bar 2
    above = 0.f;
    #pragma unroll
    for (int w = 0; w < 16; ++w)
      if (w > warp) above += tot2[w];

    float used  = val + above - S;                     // exclusive suffix sum
    float coeff = fminf(S, fmaxf(1.f - used, 0.f));
    g_C[t][b][i] = coeff;                              // coalesced in i

    // Band start: smallest i with used < 1. For all i below it, relu(1-used)=0
    // => coeff exactly 0. used is non-increasing in i so this is exact.
    bool p = (used < 1.f);
    unsigned m = __ballot_sync(0xffffffffu, p);
    if (lane == 0) wlo[warp] = m ? (warp * 32 + (__ffs(m) - 1)) : T_DIM;
    __syncthreads();                                   // bar 3
    if (i == 0) {
      int lo = T_DIM;
      #pragma unroll
      for (int w = 0; w < 16; ++w) lo = min(lo, wlo[w]);
      g_lo[t * B_DIM + b] = lo;
    }
    // bar 1 of next iteration protects wlo/tot reuse (thread 0's wlo reads
    // complete before it can reach the next writes, which sit after bar 2).
  }
}

// ---------------------------------------------------------------------------
// Kernel B: banded sparse read. One block per (t,b), 256 threads over E.
// Loads the coefficient band [lo..t] into smem, then accumulates only the
// rows with nonzero coefficient (branch is uniform across the block, so a
// zero coefficient skips the v row load entirely).
// ---------------------------------------------------------------------------
__global__ __launch_bounds__(256) void stack_read_kernel(
    const float* __restrict__ v, float* __restrict__ out) {
  const int t = blockIdx.x;
  const int b = blockIdx.y;
  const int e = threadIdx.x;

  __shared__ float cs[T_DIM];
  const int lo = g_lo[t * B_DIM + b];
  const int n  = t - lo + 1;                 // band length (>= 1 always)

  const float* Crow = &g_C[t][b][lo];
  for (int k = e; k < n; k += E_DIM) cs[k] = Crow[k];
  __syncthreads();

  float acc = 0.f;
  const float* vb = v + (size_t)b * E_DIM + e;
  for (int k = 0; k < n; ++k) {
    float c = cs[k];
    if (c != 0.f) {
      acc = fmaf(c, vb[(size_t)(lo + k) * (B_DIM * E_DIM)], acc);
    }
  }
  out[((size_t)t * B_DIM + b) * E_DIM + e] = acc;
}

// ---------------------------------------------------------------------------
// Launch: metadata order is v [T,B,E] f32, u [T,B] f32, d [T,B] f32.
// Output: reads [T,B,E] f32. Same stream => A completes before B.
// ---------------------------------------------------------------------------
extern "C" void kernel_launch(void* const* d_in, const int* in_sizes, int n_in,
                              void* d_out, int out_size) {
  const float* v = (const float*)d_in[0];
  const float* u = (const float*)d_in[1];
  const float* d = (const float*)d_in[2];
  float* out = (float*)d_out;

  stack_scan_kernel<<<B_DIM, 512>>>(u, d);

  dim3 grid(T_DIM, B_DIM);
  stack_read_kernel<<<grid, E_DIM>>>(v, out);
}